// round 7
// baseline (speedup 1.0000x reference)
#include <cuda_runtime.h>
#include <math_constants.h>

// Problem dims (fixed by setup_inputs)
#define BB 32
#define TT 2048
#define DD 1024
#define SPLITS 64
#define TC (TT / SPLITS)      // 32 rows per block
#define WARPS 8
#define RPW (TC / WARPS)      // 4 rows per warp
#define NTHR 256
#define KV 8                  // float4 per lane per row (DD/4/32)

// Scratch (no cudaMalloc allowed)
__device__ float g_scores[BB * TT];
__device__ float g_part_m[BB * SPLITS];
__device__ float g_part_z[BB * SPLITS];
__device__ float g_part_c[(size_t)BB * SPLITS * DD];
__device__ unsigned int g_count[BB];   // zero-initialized; reset by consumer

// ---------------------------------------------------------------------------
// Warp-autonomous fused kernel. Each warp streams whole rows (4KB, coalesced)
// with a private online softmax — NO block barriers in the hot loop. Warps
// merge once at block end via smem staging; atomic fan-in appoints the last
// block per batch to do the final combine.
// ---------------------------------------------------------------------------
__global__ __launch_bounds__(NTHR, 3) void dpa_fused(const float* __restrict__ q,
                                                     const float* __restrict__ v,
                                                     float* __restrict__ out) {
    const int split = blockIdx.x;
    const int b     = blockIdx.y;
    const int tid   = threadIdx.x;
    const int lane  = tid & 31;
    const int w     = tid >> 5;

    __shared__ float4 sq[DD / 4];            // 4 KB  (q row)
    __shared__ float4 stage[WARPS][DD / 4];  // 32 KB (warp partial merge)
    __shared__ float  sm_m[WARPS], sm_z[WARPS];
    __shared__ float  se[SPLITS];
    __shared__ float  sMv, sZv;
    __shared__ int    s_last;

    sq[tid] = reinterpret_cast<const float4*>(q + (size_t)b * DD)[tid];
    __syncthreads();

    float  m = -CUDART_INF_F;
    float  Z = 0.f;
    float4 c[KV];
#pragma unroll
    for (int k = 0; k < KV; k++) c[k] = make_float4(0.f, 0.f, 0.f, 0.f);

    const int t0 = split * TC + w * RPW;
    const float4* vrow0 =
        reinterpret_cast<const float4*>(v + (size_t)b * TT * DD + (size_t)t0 * DD) + lane;

    for (int r = 0; r < RPW; r++) {
        const float4* vr = vrow0 + (size_t)r * (DD / 4);

        float4 vv[KV];
#pragma unroll
        for (int k = 0; k < KV; k++) vv[k] = vr[32 * k];   // 8 coalesced loads in flight

        float p = 0.f;
#pragma unroll
        for (int k = 0; k < KV; k++) {
            const float4 qk = sq[lane + 32 * k];
            p += qk.x * vv[k].x + qk.y * vv[k].y + qk.z * vv[k].z + qk.w * vv[k].w;
        }
#pragma unroll
        for (int o = 16; o > 0; o >>= 1)
            p += __shfl_xor_sync(0xffffffffu, p, o);       // full dot on all lanes

        if (lane == 0) g_scores[b * TT + t0 + r] = p;

        const float nm = fmaxf(m, p);
        const float f  = __expf(m - nm);                   // 0 on first row
        const float e  = __expf(p - nm);
        Z = Z * f + e;
#pragma unroll
        for (int k = 0; k < KV; k++) {
            c[k].x = c[k].x * f + e * vv[k].x;
            c[k].y = c[k].y * f + e * vv[k].y;
            c[k].z = c[k].z * f + e * vv[k].z;
            c[k].w = c[k].w * f + e * vv[k].w;
        }
        m = nm;
    }

    // ---- Intra-block merge (single barrier pair) ----
    if (lane == 0) { sm_m[w] = m; sm_z[w] = Z; }
    __syncthreads();

    float Mb = sm_m[0];
#pragma unroll
    for (int j = 1; j < WARPS; j++) Mb = fmaxf(Mb, sm_m[j]);
    float Zb = 0.f;
#pragma unroll
    for (int j = 0; j < WARPS; j++) Zb += sm_z[j] * __expf(sm_m[j] - Mb);

    const float ew = __expf(m - Mb);   // this warp's rescale (m uniform across lanes)
#pragma unroll
    for (int k = 0; k < KV; k++) {
        float4 t = c[k];
        t.x *= ew; t.y *= ew; t.z *= ew; t.w *= ew;
        stage[w][lane + 32 * k] = t;
    }
    __syncthreads();

    float4 a = make_float4(0.f, 0.f, 0.f, 0.f);
#pragma unroll
    for (int j = 0; j < WARPS; j++) {
        const float4 t = stage[j][tid];
        a.x += t.x; a.y += t.y; a.z += t.z; a.w += t.w;
    }
    reinterpret_cast<float4*>(g_part_c + (size_t)(b * SPLITS + split) * DD)[tid] = a;
    if (tid == 0) {
        g_part_m[b * SPLITS + split] = Mb;
        g_part_z[b * SPLITS + split] = Zb;
    }

    // ---- Fan-in: last block per batch combines ----
    __syncthreads();
    if (tid == 0) {
        __threadfence();
        const unsigned int old = atomicAdd(&g_count[b], 1u);
        s_last = (old == SPLITS - 1);
    }
    __syncthreads();
    if (!s_last) return;
    __threadfence();

    // M, Z over 64 splits: warp 0, two elements per lane.
    if (w == 0) {
        const float m0 = g_part_m[b * SPLITS + lane];
        const float m1 = g_part_m[b * SPLITS + lane + 32];
        float M = fmaxf(m0, m1);
#pragma unroll
        for (int o = 16; o > 0; o >>= 1)
            M = fmaxf(M, __shfl_xor_sync(0xffffffffu, M, o));
        const float e0 = __expf(m0 - M);
        const float e1 = __expf(m1 - M);
        se[lane]      = e0;
        se[lane + 32] = e1;
        float z = g_part_z[b * SPLITS + lane] * e0 +
                  g_part_z[b * SPLITS + lane + 32] * e1;
#pragma unroll
        for (int o = 16; o > 0; o >>= 1)
            z += __shfl_xor_sync(0xffffffffu, z, o);
        if (lane == 0) { sMv = M; sZv = z; }
    }
    __syncthreads();

    const float M  = sMv;
    const float iZ = 1.0f / sZv;

    // Context: one float4 per thread, 64 vectorized partial loads.
    {
        const float4* pc = reinterpret_cast<const float4*>(
                               g_part_c + (size_t)b * SPLITS * DD) + tid;
        float4 acc = make_float4(0.f, 0.f, 0.f, 0.f);
#pragma unroll 16
        for (int j = 0; j < SPLITS; j++) {
            const float4 p4 = pc[(size_t)j * (DD / 4)];
            const float  e  = se[j];
            acc.x += e * p4.x; acc.y += e * p4.y; acc.z += e * p4.z; acc.w += e * p4.w;
        }
        float4 o;
        o.x = acc.x * iZ; o.y = acc.y * iZ; o.z = acc.z * iZ; o.w = acc.w * iZ;
        reinterpret_cast<float4*>(out + (size_t)b * DD)[tid] = o;
    }

    // Weights: 2048 floats per batch -> 2 float4 per thread.
    {
        const float4* sc = reinterpret_cast<const float4*>(g_scores + b * TT);
        float4* ow = reinterpret_cast<float4*>(out + (size_t)BB * DD + (size_t)b * TT);
#pragma unroll
        for (int k = 0; k < 2; k++) {
            const float4 s4 = sc[k * NTHR + tid];
            float4 wv;
            wv.x = __expf(s4.x - M) * iZ;
            wv.y = __expf(s4.y - M) * iZ;
            wv.z = __expf(s4.z - M) * iZ;
            wv.w = __expf(s4.w - M) * iZ;
            ow[k * NTHR + tid] = wv;
        }
    }

    if (tid == 0) g_count[b] = 0;   // reset for graph replay
}

extern "C" void kernel_launch(void* const* d_in, const int* in_sizes, int n_in,
                              void* d_out, int out_size) {
    const float* q = (const float*)d_in[0];   // [32,1024]
    const float* v = (const float*)d_in[1];   // [32,2048,1024]
    float* out = (float*)d_out;               // context [32*1024] ++ weights [32*2048]

    dpa_fused<<<dim3(SPLITS, BB), NTHR>>>(q, v, out);
}

// round 9
// speedup vs baseline: 1.4452x; 1.4452x over previous
#include <cuda_runtime.h>
#include <math_constants.h>
#include <cstdint>

// Problem dims (fixed by setup_inputs)
#define BB 32
#define TT 2048
#define DD 1024
#define SPLITS 64
#define TC (TT / SPLITS)      // 32 rows per block
#define NTHR 256              // one float4 lane per thread
#define STAGES 5
#define RPS 2                 // rows per stage
#define NIT (TC / RPS)        // 16 iterations

// Scratch (no cudaMalloc allowed)
__device__ float g_scores[BB * TT];
__device__ float g_part_m[BB * SPLITS];
__device__ float g_part_z[BB * SPLITS];
__device__ float g_part_c[(size_t)BB * SPLITS * DD];
__device__ unsigned int g_count[BB];   // zero-initialized; reset by consumer

__device__ __forceinline__ void cp_async16(unsigned int dst, const void* src) {
    asm volatile("cp.async.cg.shared.global [%0], [%1], 16;" :: "r"(dst), "l"(src) : "memory");
}
__device__ __forceinline__ void cp_commit() {
    asm volatile("cp.async.commit_group;" ::: "memory");
}
template <int N>
__device__ __forceinline__ void cp_wait() {
    asm volatile("cp.async.wait_group %0;" :: "n"(N) : "memory");
}

// ---------------------------------------------------------------------------
// Fused kernel, R1/R6 block-coupled shape, but with a cp.async smem ring:
// each thread prefetches its own 16B slice of rows 4 stages ahead. Since a
// thread reads back ONLY its own slice, no barrier guards stage readiness —
// prefetch streams through the reduce barriers, keeping HBM saturated.
// ---------------------------------------------------------------------------
__global__ __launch_bounds__(NTHR, 5) void dpa_fused(const float* __restrict__ q,
                                                     const float* __restrict__ v,
                                                     float* __restrict__ out) {
    const int split = blockIdx.x;
    const int b     = blockIdx.y;
    const int tid   = threadIdx.x;
    const int lane  = tid & 31;
    const int warp  = tid >> 5;

    __shared__ float4 sv[STAGES][RPS][NTHR];     // 40 KB prefetch ring
    __shared__ float  red[RPS][8];
    __shared__ float  se[SPLITS];
    __shared__ float  sMv, sZv;
    __shared__ int    s_last;

    const unsigned int sv_base =
        (unsigned int)__cvta_generic_to_shared(&sv[0][0][tid]);

    const float4 q4 = reinterpret_cast<const float4*>(q + (size_t)b * DD)[tid];

    const int t0 = split * TC;
    const float4* vb = reinterpret_cast<const float4*>(v + (size_t)b * TT * DD) + tid;

    // Prologue: prefetch stages 0..STAGES-2
#pragma unroll
    for (int st = 0; st < STAGES - 1; st++) {
#pragma unroll
        for (int r = 0; r < RPS; r++)
            cp_async16(sv_base + (unsigned int)(((st * RPS + r) * NTHR) * 16),
                       vb + (size_t)(t0 + st * RPS + r) * (DD / 4));
        cp_commit();
    }

    float  m = -CUDART_INF_F;
    float  Z = 0.0f;
    float4 c = make_float4(0.f, 0.f, 0.f, 0.f);

    for (int st = 0; st < NIT; st++) {
        cp_wait<STAGES - 2>();          // this thread's stage `st` slice has landed
        const int slot = st % STAGES;

        float4 vv[RPS];
        float  p[RPS];
#pragma unroll
        for (int r = 0; r < RPS; r++) {
            vv[r] = sv[slot][r][tid];
            p[r]  = q4.x * vv[r].x + q4.y * vv[r].y + q4.z * vv[r].z + q4.w * vv[r].w;
        }
#pragma unroll
        for (int r = 0; r < RPS; r++) {
#pragma unroll
            for (int o = 16; o > 0; o >>= 1)
                p[r] += __shfl_xor_sync(0xffffffffu, p[r], o);
        }
        if (lane == 0) {
#pragma unroll
            for (int r = 0; r < RPS; r++) red[r][warp] = p[r];
        }
        __syncthreads();

        float s[RPS];
#pragma unroll
        for (int r = 0; r < RPS; r++) {
            const float4 a0 = reinterpret_cast<const float4*>(&red[r][0])[0];
            const float4 a1 = reinterpret_cast<const float4*>(&red[r][0])[1];
            s[r] = ((a0.x + a0.y) + (a0.z + a0.w)) + ((a1.x + a1.y) + (a1.z + a1.w));
        }
        __syncthreads();   // before red reuse next iter

        if (tid < RPS) g_scores[b * TT + t0 + st * RPS + tid] = s[tid];

        // Online softmax update (identical scalar math on all threads)
        float nm = m;
#pragma unroll
        for (int r = 0; r < RPS; r++) nm = fmaxf(nm, s[r]);
        const float f = __expf(m - nm);   // 0 on first iter (m = -inf)
        Z *= f;
        c.x *= f; c.y *= f; c.z *= f; c.w *= f;
#pragma unroll
        for (int r = 0; r < RPS; r++) {
            const float e = __expf(s[r] - nm);
            Z  += e;
            c.x += e * vv[r].x;
            c.y += e * vv[r].y;
            c.z += e * vv[r].z;
            c.w += e * vv[r].w;
        }
        m = nm;

        // Prefetch stage st+STAGES-1 into the slot just freed
        const int nst = st + STAGES - 1;
        if (nst < NIT) {
            const int nslot = nst % STAGES;
#pragma unroll
            for (int r = 0; r < RPS; r++)
                cp_async16(sv_base + (unsigned int)(((nslot * RPS + r) * NTHR) * 16),
                           vb + (size_t)(t0 + nst * RPS + r) * (DD / 4));
        }
        cp_commit();   // always commit to keep group counting uniform
    }

    // Publish per-split partials
    reinterpret_cast<float4*>(g_part_c + (size_t)(b * SPLITS + split) * DD)[tid] = c;
    if (tid == 0) {
        g_part_m[b * SPLITS + split] = m;
        g_part_z[b * SPLITS + split] = Z;
    }

    // Fan-in: last block for this batch performs the combine.
    __syncthreads();
    if (tid == 0) {
        __threadfence();
        const unsigned int old = atomicAdd(&g_count[b], 1u);
        s_last = (old == SPLITS - 1);
    }
    __syncthreads();
    if (!s_last) return;
    __threadfence();

    // ---- Combine stage (one block per batch) ----
    if (warp == 0) {
        const float m0 = g_part_m[b * SPLITS + lane];
        const float m1 = g_part_m[b * SPLITS + lane + 32];
        float M = fmaxf(m0, m1);
#pragma unroll
        for (int o = 16; o > 0; o >>= 1)
            M = fmaxf(M, __shfl_xor_sync(0xffffffffu, M, o));
        const float e0 = __expf(m0 - M);
        const float e1 = __expf(m1 - M);
        se[lane]      = e0;
        se[lane + 32] = e1;
        float z = g_part_z[b * SPLITS + lane] * e0 +
                  g_part_z[b * SPLITS + lane + 32] * e1;
#pragma unroll
        for (int o = 16; o > 0; o >>= 1)
            z += __shfl_xor_sync(0xffffffffu, z, o);
        if (lane == 0) { sMv = M; sZv = z; }
    }
    __syncthreads();

    const float M  = sMv;
    const float iZ = 1.0f / sZv;

    // Context: one float4 per thread, 64 vectorized partial loads.
    {
        const float4* pc = reinterpret_cast<const float4*>(
                               g_part_c + (size_t)b * SPLITS * DD) + tid;
        float4 acc = make_float4(0.f, 0.f, 0.f, 0.f);
#pragma unroll 16
        for (int j = 0; j < SPLITS; j++) {
            const float4 p4 = pc[(size_t)j * (DD / 4)];
            const float  e  = se[j];
            acc.x += e * p4.x; acc.y += e * p4.y; acc.z += e * p4.z; acc.w += e * p4.w;
        }
        float4 o;
        o.x = acc.x * iZ; o.y = acc.y * iZ; o.z = acc.z * iZ; o.w = acc.w * iZ;
        reinterpret_cast<float4*>(out + (size_t)b * DD)[tid] = o;
    }

    // Weights: 2048 floats per batch -> 2 float4 per thread.
    {
        const float4* sc = reinterpret_cast<const float4*>(g_scores + b * TT);
        float4* ow = reinterpret_cast<float4*>(out + (size_t)BB * DD + (size_t)b * TT);
#pragma unroll
        for (int k = 0; k < 2; k++) {
            const float4 s4 = sc[k * NTHR + tid];
            float4 wv;
            wv.x = __expf(s4.x - M) * iZ;
            wv.y = __expf(s4.y - M) * iZ;
            wv.z = __expf(s4.z - M) * iZ;
            wv.w = __expf(s4.w - M) * iZ;
            ow[k * NTHR + tid] = wv;
        }
    }

    if (tid == 0) g_count[b] = 0;   // reset for graph replay
}

extern "C" void kernel_launch(void* const* d_in, const int* in_sizes, int n_in,
                              void* d_out, int out_size) {
    const float* q = (const float*)d_in[0];   // [32,1024]
    const float* v = (const float*)d_in[1];   // [32,2048,1024]
    float* out = (float*)d_out;               // context [32*1024] ++ weights [32*2048]

    dpa_fused<<<dim3(SPLITS, BB), NTHR>>>(q, v, out);
}

// round 10
// speedup vs baseline: 1.4898x; 1.0309x over previous
#include <cuda_runtime.h>
#include <math_constants.h>
#include <cstdint>

// Problem dims (fixed by setup_inputs)
#define BB 32
#define TT 2048
#define DD 1024
#define SPLITS 64
#define TC (TT / SPLITS)      // 32 rows per block
#define RPI 4                 // rows per iteration
#define NIT (TC / RPI)        // 8 iterations
#define NTHR 256              // one float4 lane per thread

// Scratch (no cudaMalloc allowed)
__device__ float g_scores[BB * TT];
__device__ float g_part_m[BB * SPLITS];
__device__ float g_part_z[BB * SPLITS];
__device__ float g_part_c[(size_t)BB * SPLITS * DD];
__device__ unsigned int g_count[BB];   // zero-initialized; reset by consumer

// ---------------------------------------------------------------------------
// Fused kernel (R6 structure) with a latency-decoupled hot loop:
//  - next iteration's rows prefetched into registers BEFORE the reduce, so
//    DRAM loads overlap the shuffle chain + barrier + softmax update
//  - double-buffered reduce staging -> ONE __syncthreads per 4 rows
//  - accumulator rescale skipped when the running max is unchanged
// ---------------------------------------------------------------------------
__global__ __launch_bounds__(NTHR, 4) void dpa_fused(const float* __restrict__ q,
                                                     const float* __restrict__ v,
                                                     float* __restrict__ out) {
    const int split = blockIdx.x;
    const int b     = blockIdx.y;
    const int tid   = threadIdx.x;
    const int lane  = tid & 31;
    const int warp  = tid >> 5;

    __shared__ float red[2][RPI][8];   // double-buffered partial staging
    __shared__ float se[SPLITS];
    __shared__ float sMv, sZv;
    __shared__ int   s_last;

    const float4 q4 = reinterpret_cast<const float4*>(q + (size_t)b * DD)[tid];

    const int t0 = split * TC;
    const float4* vb = reinterpret_cast<const float4*>(v + (size_t)b * TT * DD) + tid;

    float  m = -CUDART_INF_F;
    float  Z = 0.0f;
    float4 c = make_float4(0.f, 0.f, 0.f, 0.f);

    // Prologue: load iteration 0's rows
    float4 vv[RPI];
#pragma unroll
    for (int r = 0; r < RPI; r++)
        vv[r] = vb[(size_t)(t0 + r) * (DD / 4)];

    int par = 0;
    for (int it = 0; it < NIT; it++) {
        // Partial dots on current rows
        float p[RPI];
#pragma unroll
        for (int r = 0; r < RPI; r++)
            p[r] = q4.x * vv[r].x + q4.y * vv[r].y + q4.z * vv[r].z + q4.w * vv[r].w;

        // Prefetch NEXT iteration's rows now — in flight through the whole
        // reduce + barrier + softmax sequence below.
        float4 nx[RPI];
        if (it + 1 < NIT) {
#pragma unroll
            for (int r = 0; r < RPI; r++)
                nx[r] = vb[(size_t)(t0 + (it + 1) * RPI + r) * (DD / 4)];
        }

        // Warp reduce
#pragma unroll
        for (int r = 0; r < RPI; r++) {
#pragma unroll
            for (int o = 16; o > 0; o >>= 1)
                p[r] += __shfl_xor_sync(0xffffffffu, p[r], o);
        }
        if (lane == 0) {
#pragma unroll
            for (int r = 0; r < RPI; r++) red[par][r][warp] = p[r];
        }
        __syncthreads();   // single barrier per iteration (red is double-buffered)

        float s[RPI];
#pragma unroll
        for (int r = 0; r < RPI; r++) {
            const float4 a0 = reinterpret_cast<const float4*>(&red[par][r][0])[0];
            const float4 a1 = reinterpret_cast<const float4*>(&red[par][r][0])[1];
            s[r] = ((a0.x + a0.y) + (a0.z + a0.w)) + ((a1.x + a1.y) + (a1.z + a1.w));
        }

        if (tid < RPI) g_scores[b * TT + t0 + it * RPI + tid] = s[tid];

        // Online softmax update; rescale only when max actually moves
        float nm = m;
#pragma unroll
        for (int r = 0; r < RPI; r++) nm = fmaxf(nm, s[r]);
        if (nm > m) {                       // uniform across block
            const float f = __expf(m - nm); // 0 on first iter (m = -inf)
            Z *= f;
            c.x *= f; c.y *= f; c.z *= f; c.w *= f;
            m = nm;
        }
#pragma unroll
        for (int r = 0; r < RPI; r++) {
            const float e = __expf(s[r] - m);
            Z  += e;
            c.x += e * vv[r].x;
            c.y += e * vv[r].y;
            c.z += e * vv[r].z;
            c.w += e * vv[r].w;
        }

#pragma unroll
        for (int r = 0; r < RPI; r++) vv[r] = nx[r];
        par ^= 1;
    }

    // Publish per-split partials
    reinterpret_cast<float4*>(g_part_c + (size_t)(b * SPLITS + split) * DD)[tid] = c;
    if (tid == 0) {
        g_part_m[b * SPLITS + split] = m;
        g_part_z[b * SPLITS + split] = Z;
    }

    // Fan-in: last block for this batch performs the combine.
    __syncthreads();
    if (tid == 0) {
        __threadfence();
        const unsigned int old = atomicAdd(&g_count[b], 1u);
        s_last = (old == SPLITS - 1);
    }
    __syncthreads();
    if (!s_last) return;
    __threadfence();

    // ---- Combine stage (one block per batch) ----
    if (warp == 0) {
        const float m0 = g_part_m[b * SPLITS + lane];
        const float m1 = g_part_m[b * SPLITS + lane + 32];
        float M = fmaxf(m0, m1);
#pragma unroll
        for (int o = 16; o > 0; o >>= 1)
            M = fmaxf(M, __shfl_xor_sync(0xffffffffu, M, o));
        const float e0 = __expf(m0 - M);
        const float e1 = __expf(m1 - M);
        se[lane]      = e0;
        se[lane + 32] = e1;
        float z = g_part_z[b * SPLITS + lane] * e0 +
                  g_part_z[b * SPLITS + lane + 32] * e1;
#pragma unroll
        for (int o = 16; o > 0; o >>= 1)
            z += __shfl_xor_sync(0xffffffffu, z, o);
        if (lane == 0) { sMv = M; sZv = z; }
    }
    __syncthreads();

    const float M  = sMv;
    const float iZ = 1.0f / sZv;

    // Context: one float4 per thread, 64 vectorized partial loads.
    {
        const float4* pc = reinterpret_cast<const float4*>(
                               g_part_c + (size_t)b * SPLITS * DD) + tid;
        float4 acc = make_float4(0.f, 0.f, 0.f, 0.f);
#pragma unroll 16
        for (int j = 0; j < SPLITS; j++) {
            const float4 p4 = pc[(size_t)j * (DD / 4)];
            const float  e  = se[j];
            acc.x += e * p4.x; acc.y += e * p4.y; acc.z += e * p4.z; acc.w += e * p4.w;
        }
        float4 o;
        o.x = acc.x * iZ; o.y = acc.y * iZ; o.z = acc.z * iZ; o.w = acc.w * iZ;
        reinterpret_cast<float4*>(out + (size_t)b * DD)[tid] = o;
    }

    // Weights: 2048 floats per batch -> 2 float4 per thread.
    {
        const float4* sc = reinterpret_cast<const float4*>(g_scores + b * TT);
        float4* ow = reinterpret_cast<float4*>(out + (size_t)BB * DD + (size_t)b * TT);
#pragma unroll
        for (int k = 0; k < 2; k++) {
            const float4 s4 = sc[k * NTHR + tid];
            float4 wv;
            wv.x = __expf(s4.x - M) * iZ;
            wv.y = __expf(s4.y - M) * iZ;
            wv.z = __expf(s4.z - M) * iZ;
            wv.w = __expf(s4.w - M) * iZ;
            ow[k * NTHR + tid] = wv;
        }
    }

    if (tid == 0) g_count[b] = 0;   // reset for graph replay
}

extern "C" void kernel_launch(void* const* d_in, const int* in_sizes, int n_in,
                              void* d_out, int out_size) {
    const float* q = (const float*)d_in[0];   // [32,1024]
    const float* v = (const float*)d_in[1];   // [32,2048,1024]
    float* out = (float*)d_out;               // context [32*1024] ++ weights [32*2048]

    dpa_fused<<<dim3(SPLITS, BB), NTHR>>>(q, v, out);
}

// round 11
// speedup vs baseline: 1.6095x; 1.0804x over previous
#include <cuda_runtime.h>
#include <math_constants.h>
#include <cstdint>

// Problem dims (fixed by setup_inputs)
#define BB 32
#define TT 2048
#define DD 1024
#define SPLITS 64
#define TC (TT / SPLITS)      // 32 rows per block
#define RPI 4                 // rows per iteration
#define NTHR 256              // one float4 lane per thread

// Scratch (no cudaMalloc allowed)
__device__ float g_scores[BB * TT];
__device__ float g_part_m[BB * SPLITS];
__device__ float g_part_z[BB * SPLITS];
__device__ float g_part_c[(size_t)BB * SPLITS * DD];

// ---------------------------------------------------------------------------
// Pass 1: EXACT R1 streaming loop (46.0us, 75.8% DRAM proven). No epilogue
// beyond the partial writes — no atomics, no fences.
// ---------------------------------------------------------------------------
__global__ __launch_bounds__(NTHR) void dpa_pass1(const float* __restrict__ q,
                                                  const float* __restrict__ v) {
    const int split = blockIdx.x;
    const int b     = blockIdx.y;
    const int tid   = threadIdx.x;
    const int lane  = tid & 31;
    const int warp  = tid >> 5;

    __shared__ float red[8][RPI];

    const float4 q4 = reinterpret_cast<const float4*>(q + (size_t)b * DD)[tid];

    float  m = -CUDART_INF_F;
    float  Z = 0.0f;
    float4 c = make_float4(0.f, 0.f, 0.f, 0.f);

    const int t0 = split * TC;
    const float* vb = v + (size_t)b * TT * DD;

    for (int it = 0; it < TC; it += RPI) {
        float4 vv[RPI];
        float  p[RPI];
#pragma unroll
        for (int r = 0; r < RPI; r++) {
            vv[r] = reinterpret_cast<const float4*>(vb + (size_t)(t0 + it + r) * DD)[tid];
            p[r]  = q4.x * vv[r].x + q4.y * vv[r].y + q4.z * vv[r].z + q4.w * vv[r].w;
        }
#pragma unroll
        for (int r = 0; r < RPI; r++) {
#pragma unroll
            for (int o = 16; o > 0; o >>= 1)
                p[r] += __shfl_xor_sync(0xffffffffu, p[r], o);
        }
        if (lane == 0) {
#pragma unroll
            for (int r = 0; r < RPI; r++) red[warp][r] = p[r];
        }
        __syncthreads();

        float s[RPI];
#pragma unroll
        for (int r = 0; r < RPI; r++) {
            float acc = 0.f;
#pragma unroll
            for (int w = 0; w < 8; w++) acc += red[w][r];
            s[r] = acc;
        }
        __syncthreads();  // before smem reuse next iter

        if (tid < RPI) g_scores[b * TT + t0 + it + tid] = s[tid];

        float nm = m;
#pragma unroll
        for (int r = 0; r < RPI; r++) nm = fmaxf(nm, s[r]);
        const float f = __expf(m - nm);   // 0 on first iter (m = -inf)
        Z *= f;
        c.x *= f; c.y *= f; c.z *= f; c.w *= f;
#pragma unroll
        for (int r = 0; r < RPI; r++) {
            const float e = __expf(s[r] - nm);
            Z  += e;
            c.x += e * vv[r].x;
            c.y += e * vv[r].y;
            c.z += e * vv[r].z;
            c.w += e * vv[r].w;
        }
        m = nm;
    }

    reinterpret_cast<float4*>(g_part_c + (size_t)(b * SPLITS + split) * DD)[tid] = c;
    if (tid == 0) {
        g_part_m[b * SPLITS + split] = m;
        g_part_z[b * SPLITS + split] = Z;
    }
}

// ---------------------------------------------------------------------------
// Tail: one kernel, grid (6, BB).
//  blocks 0..3  : context. Thread = (split-group sg, d-slice di). Each thread
//                 sums 16 splits (independent __ldcg float4 loads, full MLP),
//                 then a 4-way smem merge produces this block's 64 float4.
//  blocks 4..5  : weights, one float4 per thread.
// Every block redundantly derives M/Z from the 64 (m,z) pairs (L2-resident).
// ---------------------------------------------------------------------------
__global__ __launch_bounds__(NTHR) void dpa_tail(float* __restrict__ out) {
    const int b    = blockIdx.y;
    const int part = blockIdx.x;   // 0..5
    const int tid  = threadIdx.x;
    const int lane = tid & 31;
    const int warp = tid >> 5;

    __shared__ float  se[SPLITS];
    __shared__ float  sMv, sZv;
    __shared__ float4 sacc[4][64];

    if (warp == 0) {
        const float m0 = g_part_m[b * SPLITS + lane];
        const float m1 = g_part_m[b * SPLITS + lane + 32];
        float M = fmaxf(m0, m1);
#pragma unroll
        for (int o = 16; o > 0; o >>= 1)
            M = fmaxf(M, __shfl_xor_sync(0xffffffffu, M, o));
        const float e0 = __expf(m0 - M);
        const float e1 = __expf(m1 - M);
        se[lane]      = e0;
        se[lane + 32] = e1;
        float z = g_part_z[b * SPLITS + lane] * e0 +
                  g_part_z[b * SPLITS + lane + 32] * e1;
#pragma unroll
        for (int o = 16; o > 0; o >>= 1)
            z += __shfl_xor_sync(0xffffffffu, z, o);
        if (lane == 0) { sMv = M; sZv = z; }
    }
    __syncthreads();

    const float M  = sMv;
    const float iZ = 1.0f / sZv;

    if (part < 4) {
        const int di = tid & 63;    // float4 column within this block's 64
        const int sg = tid >> 6;    // split group 0..3
        const float4* pc = reinterpret_cast<const float4*>(
                               g_part_c + (size_t)b * SPLITS * DD) + part * 64 + di;
        float4 acc = make_float4(0.f, 0.f, 0.f, 0.f);
#pragma unroll
        for (int j = sg; j < SPLITS; j += 4) {       // 16 independent loads
            const float4 p4 = __ldcg(&pc[(size_t)j * (DD / 4)]);
            const float  e  = se[j];
            acc.x += e * p4.x; acc.y += e * p4.y; acc.z += e * p4.z; acc.w += e * p4.w;
        }
        sacc[sg][di] = acc;
        __syncthreads();
        if (sg == 0) {
            const float4 a0 = sacc[0][di], a1 = sacc[1][di];
            const float4 a2 = sacc[2][di], a3 = sacc[3][di];
            float4 o;
            o.x = (a0.x + a1.x + a2.x + a3.x) * iZ;
            o.y = (a0.y + a1.y + a2.y + a3.y) * iZ;
            o.z = (a0.z + a1.z + a2.z + a3.z) * iZ;
            o.w = (a0.w + a1.w + a2.w + a3.w) * iZ;
            reinterpret_cast<float4*>(out + (size_t)b * DD)[part * 64 + di] = o;
        }
    } else {
        const int i4 = (part - 4) * NTHR + tid;       // 0..511 float4 -> 2048 weights
        const float4 s4 = __ldcg(
            &reinterpret_cast<const float4*>(g_scores + b * TT)[i4]);
        float4 w;
        w.x = __expf(s4.x - M) * iZ;
        w.y = __expf(s4.y - M) * iZ;
        w.z = __expf(s4.z - M) * iZ;
        w.w = __expf(s4.w - M) * iZ;
        reinterpret_cast<float4*>(out + (size_t)BB * DD + (size_t)b * TT)[i4] = w;
    }
}

extern "C" void kernel_launch(void* const* d_in, const int* in_sizes, int n_in,
                              void* d_out, int out_size) {
    const float* q = (const float*)d_in[0];   // [32,1024]
    const float* v = (const float*)d_in[1];   // [32,2048,1024]
    float* out = (float*)d_out;               // context [32*1024] ++ weights [32*2048]

    dpa_pass1<<<dim3(SPLITS, BB), NTHR>>>(q, v);
    dpa_tail<<<dim3(6, BB), NTHR>>>(out);
}

// round 12
// speedup vs baseline: 1.6650x; 1.0345x over previous
#include <cuda_runtime.h>
#include <math_constants.h>
#include <cstdint>

// Problem dims (fixed by setup_inputs)
#define BB 32
#define TT 2048
#define DD 1024
#define SPLITS 64
#define TC (TT / SPLITS)      // 32 rows per block
#define RPI 4                 // rows per iteration
#define NTHR 256              // one float4 lane per thread

// Scratch (no cudaMalloc allowed)
__device__ float g_scores[BB * TT];
__device__ float g_part_m[BB * SPLITS];
__device__ float g_part_z[BB * SPLITS];
__device__ float g_part_c[(size_t)BB * SPLITS * DD];

// ---------------------------------------------------------------------------
// Pass 1: proven streaming loop (unchanged from R11).
// ---------------------------------------------------------------------------
__global__ __launch_bounds__(NTHR) void dpa_pass1(const float* __restrict__ q,
                                                  const float* __restrict__ v) {
    const int split = blockIdx.x;
    const int b     = blockIdx.y;
    const int tid   = threadIdx.x;
    const int lane  = tid & 31;
    const int warp  = tid >> 5;

    __shared__ float red[8][RPI];

    const float4 q4 = reinterpret_cast<const float4*>(q + (size_t)b * DD)[tid];

    float  m = -CUDART_INF_F;
    float  Z = 0.0f;
    float4 c = make_float4(0.f, 0.f, 0.f, 0.f);

    const int t0 = split * TC;
    const float* vb = v + (size_t)b * TT * DD;

    for (int it = 0; it < TC; it += RPI) {
        float4 vv[RPI];
        float  p[RPI];
#pragma unroll
        for (int r = 0; r < RPI; r++) {
            vv[r] = reinterpret_cast<const float4*>(vb + (size_t)(t0 + it + r) * DD)[tid];
            p[r]  = q4.x * vv[r].x + q4.y * vv[r].y + q4.z * vv[r].z + q4.w * vv[r].w;
        }
#pragma unroll
        for (int r = 0; r < RPI; r++) {
#pragma unroll
            for (int o = 16; o > 0; o >>= 1)
                p[r] += __shfl_xor_sync(0xffffffffu, p[r], o);
        }
        if (lane == 0) {
#pragma unroll
            for (int r = 0; r < RPI; r++) red[warp][r] = p[r];
        }
        __syncthreads();

        float s[RPI];
#pragma unroll
        for (int r = 0; r < RPI; r++) {
            float acc = 0.f;
#pragma unroll
            for (int w = 0; w < 8; w++) acc += red[w][r];
            s[r] = acc;
        }
        __syncthreads();  // before smem reuse next iter

        if (tid < RPI) g_scores[b * TT + t0 + it + tid] = s[tid];

        float nm = m;
#pragma unroll
        for (int r = 0; r < RPI; r++) nm = fmaxf(nm, s[r]);
        const float f = __expf(m - nm);   // 0 on first iter (m = -inf)
        Z *= f;
        c.x *= f; c.y *= f; c.z *= f; c.w *= f;
#pragma unroll
        for (int r = 0; r < RPI; r++) {
            const float e = __expf(s[r] - nm);
            Z  += e;
            c.x += e * vv[r].x;
            c.y += e * vv[r].y;
            c.z += e * vv[r].z;
            c.w += e * vv[r].w;
        }
        m = nm;
    }

    reinterpret_cast<float4*>(g_part_c + (size_t)(b * SPLITS + split) * DD)[tid] = c;
    if (tid == 0) {
        g_part_m[b * SPLITS + split] = m;
        g_part_z[b * SPLITS + split] = Z;
    }
}

// ---------------------------------------------------------------------------
// Tail, grid (10, BB), latency-overlapped:
//  - DATA LOADS ISSUE FIRST (independent of M/Z), overlapping the preamble's
//    own DRAM load + shuffle reduce. One DRAM epoch instead of two.
//  blocks 0..7 : context. Thread = (sg = tid>>5, di = tid&31); 8 coalesced
//                __ldcg float4 loads each; 8-way smem merge.
//  blocks 8..9 : weights, one float4 per thread.
// ---------------------------------------------------------------------------
__global__ __launch_bounds__(NTHR) void dpa_tail(float* __restrict__ out) {
    const int b    = blockIdx.y;
    const int part = blockIdx.x;   // 0..9
    const int tid  = threadIdx.x;
    const int lane = tid & 31;
    const int warp = tid >> 5;

    __shared__ float  se[SPLITS];
    __shared__ float  sMv, sZv;
    __shared__ float4 sacc[8][32];

    // ---- Phase 0: issue independent data loads immediately ----
    float4 pv[8];
    float4 s4;
    if (part < 8) {
        const int di = lane;        // float4 column within this block's 32
        const int sg = warp;        // split group 0..7
        const float4* pc = reinterpret_cast<const float4*>(
                               g_part_c + (size_t)b * SPLITS * DD) + part * 32 + di;
#pragma unroll
        for (int k = 0; k < 8; k++)   // splits j = sg + 8k — all independent
            pv[k] = __ldcg(&pc[(size_t)(sg + 8 * k) * (DD / 4)]);
    } else {
        const int i4 = (part - 8) * NTHR + tid;   // 0..511 float4 per batch
        s4 = __ldcg(&reinterpret_cast<const float4*>(g_scores + b * TT)[i4]);
    }

    // ---- Preamble (overlaps the loads above) ----
    if (warp == 0) {
        const float m0 = g_part_m[b * SPLITS + lane];
        const float m1 = g_part_m[b * SPLITS + lane + 32];
        float M = fmaxf(m0, m1);
#pragma unroll
        for (int o = 16; o > 0; o >>= 1)
            M = fmaxf(M, __shfl_xor_sync(0xffffffffu, M, o));
        const float e0 = __expf(m0 - M);
        const float e1 = __expf(m1 - M);
        se[lane]      = e0;
        se[lane + 32] = e1;
        float z = g_part_z[b * SPLITS + lane] * e0 +
                  g_part_z[b * SPLITS + lane + 32] * e1;
#pragma unroll
        for (int o = 16; o > 0; o >>= 1)
            z += __shfl_xor_sync(0xffffffffu, z, o);
        if (lane == 0) { sMv = M; sZv = z; }
    }
    __syncthreads();

    const float M  = sMv;
    const float iZ = 1.0f / sZv;

    if (part < 8) {
        const int di = lane;
        const int sg = warp;
        float4 acc = make_float4(0.f, 0.f, 0.f, 0.f);
#pragma unroll
        for (int k = 0; k < 8; k++) {
            const float e = se[sg + 8 * k];
            acc.x += e * pv[k].x; acc.y += e * pv[k].y;
            acc.z += e * pv[k].z; acc.w += e * pv[k].w;
        }
        sacc[sg][di] = acc;
        __syncthreads();
        if (warp == 0) {
            float4 o = sacc[0][di];
#pragma unroll
            for (int j = 1; j < 8; j++) {
                const float4 a = sacc[j][di];
                o.x += a.x; o.y += a.y; o.z += a.z; o.w += a.w;
            }
            o.x *= iZ; o.y *= iZ; o.z *= iZ; o.w *= iZ;
            reinterpret_cast<float4*>(out + (size_t)b * DD)[part * 32 + di] = o;
        }
    } else {
        const int i4 = (part - 8) * NTHR + tid;
        float4 w;
        w.x = __expf(s4.x - M) * iZ;
        w.y = __expf(s4.y - M) * iZ;
        w.z = __expf(s4.z - M) * iZ;
        w.w = __expf(s4.w - M) * iZ;
        reinterpret_cast<float4*>(out + (size_t)BB * DD + (size_t)b * TT)[i4] = w;
    }
}

extern "C" void kernel_launch(void* const* d_in, const int* in_sizes, int n_in,
                              void* d_out, int out_size) {
    const float* q = (const float*)d_in[0];   // [32,1024]
    const float* v = (const float*)d_in[1];   // [32,2048,1024]
    float* out = (float*)d_out;               // context [32*1024] ++ weights [32*2048]

    dpa_pass1<<<dim3(SPLITS, BB), NTHR>>>(q, v);
    dpa_tail<<<dim3(10, BB), NTHR>>>(out);
}

// round 13
// speedup vs baseline: 1.7411x; 1.0457x over previous
#include <cuda_runtime.h>
#include <math_constants.h>
#include <cstdint>

// Problem dims (fixed by setup_inputs)
#define BB 32
#define TT 2048
#define DD 1024
#define SPLITS 64
#define TC (TT / SPLITS)      // 32 rows per block
#define RPI 4                 // rows per iteration
#define NTHR 256              // one float4 lane per thread

// Scratch (no cudaMalloc allowed)
__device__ float g_scores[BB * TT];
__device__ float g_part_m[BB * SPLITS];
__device__ float g_part_z[BB * SPLITS];
__device__ float g_part_c[(size_t)BB * SPLITS * DD];

// ---------------------------------------------------------------------------
// Pass 1: proven streaming loop; v is read via __ldcs (evict-first) so the
// 256MB single-use stream does NOT evict the 8MB of partials from L2 —
// the tail then combines from L2 hits instead of DRAM.
// ---------------------------------------------------------------------------
__global__ __launch_bounds__(NTHR) void dpa_pass1(const float* __restrict__ q,
                                                  const float* __restrict__ v) {
    const int split = blockIdx.x;
    const int b     = blockIdx.y;
    const int tid   = threadIdx.x;
    const int lane  = tid & 31;
    const int warp  = tid >> 5;

    __shared__ float red[8][RPI];

    const float4 q4 = reinterpret_cast<const float4*>(q + (size_t)b * DD)[tid];

    float  m = -CUDART_INF_F;
    float  Z = 0.0f;
    float4 c = make_float4(0.f, 0.f, 0.f, 0.f);

    const int t0 = split * TC;
    const float* vb = v + (size_t)b * TT * DD;

    for (int it = 0; it < TC; it += RPI) {
        float4 vv[RPI];
        float  p[RPI];
#pragma unroll
        for (int r = 0; r < RPI; r++) {
            vv[r] = __ldcs(
                &reinterpret_cast<const float4*>(vb + (size_t)(t0 + it + r) * DD)[tid]);
            p[r]  = q4.x * vv[r].x + q4.y * vv[r].y + q4.z * vv[r].z + q4.w * vv[r].w;
        }
#pragma unroll
        for (int r = 0; r < RPI; r++) {
#pragma unroll
            for (int o = 16; o > 0; o >>= 1)
                p[r] += __shfl_xor_sync(0xffffffffu, p[r], o);
        }
        if (lane == 0) {
#pragma unroll
            for (int r = 0; r < RPI; r++) red[warp][r] = p[r];
        }
        __syncthreads();

        float s[RPI];
#pragma unroll
        for (int r = 0; r < RPI; r++) {
            float acc = 0.f;
#pragma unroll
            for (int w = 0; w < 8; w++) acc += red[w][r];
            s[r] = acc;
        }
        __syncthreads();  // before smem reuse next iter

        if (tid < RPI) g_scores[b * TT + t0 + it + tid] = s[tid];

        float nm = m;
#pragma unroll
        for (int r = 0; r < RPI; r++) nm = fmaxf(nm, s[r]);
        const float f = __expf(m - nm);   // 0 on first iter (m = -inf)
        Z *= f;
        c.x *= f; c.y *= f; c.z *= f; c.w *= f;
#pragma unroll
        for (int r = 0; r < RPI; r++) {
            const float e = __expf(s[r] - nm);
            Z  += e;
            c.x += e * vv[r].x;
            c.y += e * vv[r].y;
            c.z += e * vv[r].z;
            c.w += e * vv[r].w;
        }
        m = nm;
    }

    reinterpret_cast<float4*>(g_part_c + (size_t)(b * SPLITS + split) * DD)[tid] = c;
    if (tid == 0) {
        g_part_m[b * SPLITS + split] = m;
        g_part_z[b * SPLITS + split] = Z;
    }
}

// ---------------------------------------------------------------------------
// Tail, grid (10, BB): data loads issue first (overlapping the M/Z preamble);
// with the .CS change in pass1 these should now be L2 hits.
//  blocks 0..7 : context (8 loads/thread, 8-way smem merge)
//  blocks 8..9 : weights
// ---------------------------------------------------------------------------
__global__ __launch_bounds__(NTHR) void dpa_tail(float* __restrict__ out) {
    const int b    = blockIdx.y;
    const int part = blockIdx.x;   // 0..9
    const int tid  = threadIdx.x;
    const int lane = tid & 31;
    const int warp = tid >> 5;

    __shared__ float  se[SPLITS];
    __shared__ float  sMv, sZv;
    __shared__ float4 sacc[8][32];

    // ---- Phase 0: issue independent data loads immediately ----
    float4 pv[8];
    float4 s4;
    if (part < 8) {
        const int di = lane;        // float4 column within this block's 32
        const int sg = warp;        // split group 0..7
        const float4* pc = reinterpret_cast<const float4*>(
                               g_part_c + (size_t)b * SPLITS * DD) + part * 32 + di;
#pragma unroll
        for (int k = 0; k < 8; k++)   // splits j = sg + 8k — all independent
            pv[k] = __ldg(&pc[(size_t)(sg + 8 * k) * (DD / 4)]);
    } else {
        const int i4 = (part - 8) * NTHR + tid;   // 0..511 float4 per batch
        s4 = __ldg(&reinterpret_cast<const float4*>(g_scores + b * TT)[i4]);
    }

    // ---- Preamble (overlaps the loads above) ----
    if (warp == 0) {
        const float m0 = g_part_m[b * SPLITS + lane];
        const float m1 = g_part_m[b * SPLITS + lane + 32];
        float M = fmaxf(m0, m1);
#pragma unroll
        for (int o = 16; o > 0; o >>= 1)
            M = fmaxf(M, __shfl_xor_sync(0xffffffffu, M, o));
        const float e0 = __expf(m0 - M);
        const float e1 = __expf(m1 - M);
        se[lane]      = e0;
        se[lane + 32] = e1;
        float z = g_part_z[b * SPLITS + lane] * e0 +
                  g_part_z[b * SPLITS + lane + 32] * e1;
#pragma unroll
        for (int o = 16; o > 0; o >>= 1)
            z += __shfl_xor_sync(0xffffffffu, z, o);
        if (lane == 0) { sMv = M; sZv = z; }
    }
    __syncthreads();

    const float M  = sMv;
    const float iZ = 1.0f / sZv;

    if (part < 8) {
        const int di = lane;
        const int sg = warp;
        float4 acc = make_float4(0.f, 0.f, 0.f, 0.f);
#pragma unroll
        for (int k = 0; k < 8; k++) {
            const float e = se[sg + 8 * k];
            acc.x += e * pv[k].x; acc.y += e * pv[k].y;
            acc.z += e * pv[k].z; acc.w += e * pv[k].w;
        }
        sacc[sg][di] = acc;
        __syncthreads();
        if (warp == 0) {
            float4 o = sacc[0][di];
#pragma unroll
            for (int j = 1; j < 8; j++) {
                const float4 a = sacc[j][di];
                o.x += a.x; o.y += a.y; o.z += a.z; o.w += a.w;
            }
            o.x *= iZ; o.y *= iZ; o.z *= iZ; o.w *= iZ;
            reinterpret_cast<float4*>(out + (size_t)b * DD)[part * 32 + di] = o;
        }
    } else {
        const int i4 = (part - 8) * NTHR + tid;
        float4 w;
        w.x = __expf(s4.x - M) * iZ;
        w.y = __expf(s4.y - M) * iZ;
        w.z = __expf(s4.z - M) * iZ;
        w.w = __expf(s4.w - M) * iZ;
        reinterpret_cast<float4*>(out + (size_t)BB * DD + (size_t)b * TT)[i4] = w;
    }
}

extern "C" void kernel_launch(void* const* d_in, const int* in_sizes, int n_in,
                              void* d_out, int out_size) {
    const float* q = (const float*)d_in[0];   // [32,1024]
    const float* v = (const float*)d_in[1];   // [32,2048,1024]
    float* out = (float*)d_out;               // context [32*1024] ++ weights [32*2048]

    dpa_pass1<<<dim3(SPLITS, BB), NTHR>>>(q, v);
    dpa_tail<<<dim3(10, BB), NTHR>>>(out);
}